// round 10
// baseline (speedup 1.0000x reference)
#include <cuda_runtime.h>
#include <cuda_fp16.h>
#include <cstdint>

// ---------------- problem dims ----------------
#define MROWS 32768           // 4*8192 activation rows
#define KDIM  512
#define NDIM  512
#define KD2   1024            // concatenated K: [a_hi | a_lo]

// ---------------- GEMM tiling -----------------
#define BM 128
#define BN 128
#define BK 64
#define STAGES 3
#define STAGE_OP_BYTES (128 * 128)            // one operand, one stage: 128 rows x 128 B
#define STAGE_BYTES (2 * STAGE_OP_BYTES)      // A + B
#define SMEM_DYN (STAGES * STAGE_BYTES)       // 98304 B -> 2 CTAs/SM

#define PREP_GRID 296                          // 2 blocks/SM -> guaranteed co-residency

// ---------------- scratch ---------------------
// A2[m, 0:512]  = rint(x/s_hi)            (ints, fp16-exact, |.|<=2048)
// A2[m,512:1024]= rint(r*2048/s_hi)/2048  (x_lo/s_hi, fp16-exact)
// B2[n, 0:512]  = fp16(w[n,:]) ; B2[n,512:1024] = same (duplicated)
__device__ __half  g_A2[(size_t)MROWS * KD2];  // 64 MB
__device__ __half  g_B2[(size_t)NDIM * KD2];   //  1 MB
__device__ unsigned g_scal[1];                 // absmax bits of x
__device__ unsigned g_cnt, g_cnt2;             // software grid barrier (self-resetting)
// NOTE: no zeroing kernel. Zero-init at module load covers the first call; on
// replays atomicMax re-submits the identical deterministic max (idempotent),
// and the barrier counters return to 0 before each kernel exit.

// ---------------- helpers ---------------------
__device__ __forceinline__ float load_scale_x() {
    float mv = fmaxf(__uint_as_float(g_scal[0]), 1e-30f);
    return exp2f(ceilf(log2f(mv)) - 11.f);     // s_hi (13-bit split)
}

__device__ __forceinline__ uint32_t smem_u32(const void* p) {
    return (uint32_t)__cvta_generic_to_shared(p);
}

__device__ __forceinline__ void block_max_atomic(float m, int slot) {
    #pragma unroll
    for (int o = 16; o; o >>= 1) m = fmaxf(m, __shfl_xor_sync(0xffffffffu, m, o));
    __shared__ float sm[32];
    int warp = threadIdx.x >> 5, lane = threadIdx.x & 31;
    if (lane == 0) sm[warp] = m;
    __syncthreads();
    if (warp == 0) {
        int nw = (blockDim.x + 31) >> 5;
        m = (lane < nw) ? sm[lane] : 0.f;
        #pragma unroll
        for (int o = 16; o; o >>= 1) m = fmaxf(m, __shfl_xor_sync(0xffffffffu, m, o));
        if (lane == 0) atomicMax(&g_scal[slot], __float_as_uint(m));
    }
}

// ---------------- fused prep ------------------
// Phase A: grid-wide max|x| -> g_scal[0].
// Software barrier (all 296 blocks are co-resident at 2 blocks/SM).
// Phase B: quantize x -> A2 (x re-read is L2-resident: 64 MB < L2), w -> B2.
__global__ void __launch_bounds__(256, 2) k_prep(const float* __restrict__ x,
                                                 const float* __restrict__ w) {
    const int tid = threadIdx.x;
    const size_t gtid = (size_t)blockIdx.x * blockDim.x + tid;
    const size_t gstride = (size_t)PREP_GRID * 256;

    // ---- Phase A: absmax over x ----
    {
        size_t n4 = (size_t)MROWS * KDIM / 4;
        float m0 = 0.f, m1 = 0.f;
        size_t i = gtid;
        for (; i + gstride < n4; i += 2 * gstride) {
            float4 v = ((const float4*)x)[i];
            float4 u = ((const float4*)x)[i + gstride];
            m0 = fmaxf(m0, fmaxf(fmaxf(fabsf(v.x), fabsf(v.y)), fmaxf(fabsf(v.z), fabsf(v.w))));
            m1 = fmaxf(m1, fmaxf(fmaxf(fabsf(u.x), fabsf(u.y)), fmaxf(fabsf(u.z), fabsf(u.w))));
        }
        if (i < n4) {
            float4 v = ((const float4*)x)[i];
            m0 = fmaxf(m0, fmaxf(fmaxf(fabsf(v.x), fabsf(v.y)), fmaxf(fabsf(v.z), fabsf(v.w))));
        }
        block_max_atomic(fmaxf(m0, m1), 0);
    }

    // ---- Grid barrier (self-resetting two-counter) ----
    __threadfence();
    if (tid == 0) {
        atomicAdd(&g_cnt, 1u);
        while (*(volatile unsigned*)&g_cnt < (unsigned)PREP_GRID) { __nanosleep(64); }
        unsigned o2 = atomicAdd(&g_cnt2, 1u);
        if (o2 == (unsigned)(PREP_GRID - 1)) {   // last passer resets for next launch
            *(volatile unsigned*)&g_cnt = 0u;
            __threadfence();
            *(volatile unsigned*)&g_cnt2 = 0u;
        }
    }
    __syncthreads();

    // ---- Phase B: quantize ----
    __half2* A2 = (__half2*)g_A2;
    __half2* B2 = (__half2*)g_B2;
    const float sh = load_scale_x();
    const float invh = 1.f / sh;
    const float invl = 2048.f / sh;
    const float rs = 1.f / 2048.f;

    {   // x -> both K-halves of A2 (s_lo = s_hi/2048; a wrong guess perturbs
        // the output by ~2e-5 relative — negligible)
        size_t n4 = (size_t)MROWS * KDIM / 4;
        for (size_t i = gtid; i < n4; i += gstride) {
            float4 v = ((const float4*)x)[i];
            size_t m = i >> 7;            // / (512/4)
            size_t kq = i & 127;
            float a0 = rintf(v.x * invh), a1 = rintf(v.y * invh);
            float a2v = rintf(v.z * invh), a3 = rintf(v.w * invh);
            float r0 = v.x - a0 * sh, r1 = v.y - a1 * sh;
            float r2 = v.z - a2v * sh, r3 = v.w - a3 * sh;
            size_t hi = m * (KD2 / 2) + kq * 2;       // half2 units
            A2[hi]     = __floats2half2_rn(a0, a1);
            A2[hi + 1] = __floats2half2_rn(a2v, a3);
            A2[hi + 256]     = __floats2half2_rn(rintf(r0 * invl) * rs, rintf(r1 * invl) * rs);
            A2[hi + 256 + 1] = __floats2half2_rn(rintf(r2 * invl) * rs, rintf(r3 * invl) * rs);
        }
    }
    {   // w -> B2 (duplicated across the two K-halves)
        size_t n4 = (size_t)NDIM * KDIM / 4;
        for (size_t i = gtid; i < n4; i += gstride) {
            float4 v = ((const float4*)w)[i];
            size_t n = i >> 7;
            size_t kq = i & 127;
            __half2 p0 = __floats2half2_rn(v.x, v.y);
            __half2 p1 = __floats2half2_rn(v.z, v.w);
            size_t b = n * (KD2 / 2) + kq * 2;
            B2[b] = p0; B2[b + 1] = p1;               // K-half 0
            B2[b + 256] = p0; B2[b + 256 + 1] = p1;   // K-half 1 (duplicate)
        }
    }
}

// ---------------- HMMA GEMM -------------------
// out[m][n] = s_hi * sum_k A2[m,k]*B2[n,k];  128x128 tile, BK=64, 3 stages
// (wait_group 1 -> loads get 2 compute-blocks of slack), XOR-swizzled smem
// (no pad), 2 CTAs/SM. K=1024 covers both precision planes in one chain.
extern __shared__ __half dynsmem[];

// Swizzled store layout per operand-stage: 128 rows x 8 chunks of 16B;
// chunk c of row r lives at physical chunk c ^ (r & 7).
__device__ __forceinline__ void gemm_load_stage(uint32_t smem_base_u32, int s, int kt,
                                                size_t a_base, size_t b_base) {
    const int tid = threadIdx.x;
    const uint32_t As = smem_base_u32 + (uint32_t)s * STAGE_BYTES;
    const uint32_t Bs = As + STAGE_OP_BYTES;
    const int k0 = kt * BK;
    #pragma unroll
    for (int i = 0; i < 8; ++i) {
        int id = tid + i * 256;              // 0..2047 chunks of 16B
        bool isA = id < 1024;
        int loc = isA ? id : id - 1024;
        int row = loc >> 3, cc = loc & 7;
        const __half* src = isA
            ? &g_A2[a_base + (size_t)row * KD2 + k0 + cc * 8]
            : &g_B2[b_base + (size_t)row * KD2 + k0 + cc * 8];
        uint32_t phys = (uint32_t)(cc ^ (row & 7));
        uint32_t dst = (isA ? As : Bs) + (uint32_t)row * 128u + phys * 16u;
        asm volatile("cp.async.cg.shared.global [%0], [%1], 16;\n" :: "r"(dst), "l"(src));
    }
}

__global__ void __launch_bounds__(256, 2) k_gemm3(float* __restrict__ out) {
    const int bn = blockIdx.x, bm = blockIdx.y;
    const int tid = threadIdx.x;
    const int wid = tid >> 5, lane = tid & 31;
    const int warp_m = wid & 1;          // 0..1 -> 64 rows each
    const int warp_n = wid >> 1;         // 0..3 -> 32 cols each

    const uint32_t sb = smem_u32(dynsmem);
    const size_t a_base = (size_t)bm * BM * KD2;
    const size_t b_base = (size_t)bn * BN * KD2;

    float acc[4][4][4];
    #pragma unroll
    for (int i = 0; i < 4; i++)
        #pragma unroll
        for (int j = 0; j < 4; j++)
            #pragma unroll
            for (int k = 0; k < 4; k++) acc[i][j][k] = 0.f;

    gemm_load_stage(sb, 0, 0, a_base, b_base);
    asm volatile("cp.async.commit_group;\n");
    gemm_load_stage(sb, 1, 1, a_base, b_base);
    asm volatile("cp.async.commit_group;\n");

    const int KT = KD2 / BK;   // 16
    for (int kt = 0; kt < KT; ++kt) {
        if (kt == KT - 1) { asm volatile("cp.async.wait_group 0;\n"); }
        else              { asm volatile("cp.async.wait_group 1;\n"); }
        __syncthreads();
        // Stage (kt+2)%3 was consumed in iteration kt-1; safe to refill after
        // the barrier. Load overlaps ~2 full compute blocks.
        if (kt + 2 < KT) {
            gemm_load_stage(sb, (kt + 2) % STAGES, kt + 2, a_base, b_base);
            asm volatile("cp.async.commit_group;\n");
        }

        const uint32_t As = sb + (uint32_t)(kt % STAGES) * STAGE_BYTES;
        const uint32_t Bs = As + STAGE_OP_BYTES;

        #pragma unroll
        for (int ks = 0; ks < BK / 16; ++ks) {
            uint32_t a[4][4];
            #pragma unroll
            for (int mf = 0; mf < 4; ++mf) {
                int row = warp_m * 64 + mf * 16 + (lane & 15);
                int chunk = ks * 2 + ((lane & 16) ? 1 : 0);
                uint32_t addr = As + (uint32_t)row * 128u
                              + (uint32_t)(chunk ^ (row & 7)) * 16u;
                asm volatile("ldmatrix.sync.aligned.m8n8.x4.shared.b16 {%0,%1,%2,%3}, [%4];"
                             : "=r"(a[mf][0]), "=r"(a[mf][1]), "=r"(a[mf][2]), "=r"(a[mf][3])
                             : "r"(addr));
            }
            uint32_t b[4][2];
            #pragma unroll
            for (int g = 0; g < 2; ++g) {
                int nrow = warp_n * 32 + g * 16 + ((lane >> 4) << 3) + (lane & 7);
                int chunk = ks * 2 + ((lane & 8) ? 1 : 0);
                uint32_t addr = Bs + (uint32_t)nrow * 128u
                              + (uint32_t)(chunk ^ (nrow & 7)) * 16u;
                asm volatile("ldmatrix.sync.aligned.m8n8.x4.shared.b16 {%0,%1,%2,%3}, [%4];"
                             : "=r"(b[g * 2][0]), "=r"(b[g * 2][1]),
                               "=r"(b[g * 2 + 1][0]), "=r"(b[g * 2 + 1][1])
                             : "r"(addr));
            }
            #pragma unroll
            for (int mf = 0; mf < 4; ++mf)
                #pragma unroll
                for (int nf = 0; nf < 4; ++nf) {
                    asm volatile(
                        "mma.sync.aligned.m16n8k16.row.col.f32.f16.f16.f32 "
                        "{%0,%1,%2,%3}, {%4,%5,%6,%7}, {%8,%9}, {%0,%1,%2,%3};"
                        : "+f"(acc[mf][nf][0]), "+f"(acc[mf][nf][1]),
                          "+f"(acc[mf][nf][2]), "+f"(acc[mf][nf][3])
                        : "r"(a[mf][0]), "r"(a[mf][1]), "r"(a[mf][2]), "r"(a[mf][3]),
                          "r"(b[nf][0]), "r"(b[nf][1]));
                }
        }
    }

    // Epilogue: out = s_hi * acc, straight to d_out.
    const float f = load_scale_x();
    const size_t obase = (size_t)bm * BM * NDIM + (size_t)bn * BN;
    #pragma unroll
    for (int mf = 0; mf < 4; ++mf)
        #pragma unroll
        for (int nf = 0; nf < 4; ++nf) {
            int r0 = warp_m * 64 + mf * 16 + (lane >> 2);
            int c0 = warp_n * 32 + nf * 8 + 2 * (lane & 3);
            float* op = &out[obase + (size_t)r0 * NDIM + c0];
            op[0] = acc[mf][nf][0] * f;
            op[1] = acc[mf][nf][1] * f;
            float* op2 = op + 8 * NDIM;
            op2[0] = acc[mf][nf][2] * f;
            op2[1] = acc[mf][nf][3] * f;
        }
}

// ---------------- launch ----------------------
extern "C" void kernel_launch(void* const* d_in, const int* in_sizes, int n_in,
                              void* d_out, int out_size) {
    const float* x = (const float*)d_in[0];
    const float* w = (const float*)d_in[1];
    if (n_in >= 2 && in_sizes[0] == NDIM * KDIM && in_sizes[1] == MROWS * KDIM) {
        const float* t = x; x = w; w = t;
    }

    cudaFuncSetAttribute(k_gemm3, cudaFuncAttributeMaxDynamicSharedMemorySize, SMEM_DYN);

    k_prep<<<PREP_GRID, 256>>>(x, w);                                       // launch 1
    k_gemm3<<<dim3(NDIM / BN, MROWS / BM), 256, SMEM_DYN>>>((float*)d_out); // launch 2 (even ncu slots)
}

// round 11
// speedup vs baseline: 1.0080x; 1.0080x over previous
#include <cuda_runtime.h>
#include <cuda_fp16.h>
#include <cstdint>

// ---------------- problem dims ----------------
#define MROWS 32768           // 4*8192 activation rows
#define KDIM  512
#define NDIM  512
#define KD2   1024            // concatenated K: [a_hi | a_lo]

// ---------------- GEMM tiling -----------------
#define BM 128
#define BN 64
#define BK 64
#define STAGES 3
#define A_STAGE_BYTES (BM * 128)              // 16384
#define B_STAGE_BYTES (BN * 128)              // 8192
#define STAGE_BYTES (A_STAGE_BYTES + B_STAGE_BYTES)   // 24576
#define SMEM_DYN (STAGES * STAGE_BYTES)       // 73728 -> 3 CTAs/SM

// ---------------- scratch ---------------------
// A2[m, 0:512]  = rint(x/s_hi)            (ints, fp16-exact, |.|<=2048)
// A2[m,512:1024]= rint(r*2048/s_hi)/2048  (x_lo/s_hi, fp16-exact)
// B2[n, 0:512]  = fp16(w[n,:]) ; B2[n,512:1024] = same (duplicated)
__device__ __half  g_A2[(size_t)MROWS * KD2];  // 64 MB
__device__ __half  g_B2[(size_t)NDIM * KD2];   //  1 MB
__device__ unsigned g_scal[1];                 // absmax bits of x
// NOTE: no zeroing kernel. Zero-init at module load covers the first call; on
// replays atomicMax re-submits the identical deterministic max (idempotent).

// ---------------- helpers ---------------------
__device__ __forceinline__ float load_scale_x() {
    float mv = fmaxf(__uint_as_float(g_scal[0]), 1e-30f);
    return exp2f(ceilf(log2f(mv)) - 11.f);     // s_hi (13-bit split)
}

__device__ __forceinline__ uint32_t smem_u32(const void* p) {
    return (uint32_t)__cvta_generic_to_shared(p);
}

__device__ __forceinline__ void block_max_atomic(float m, int slot) {
    #pragma unroll
    for (int o = 16; o; o >>= 1) m = fmaxf(m, __shfl_xor_sync(0xffffffffu, m, o));
    __shared__ float sm[32];
    int warp = threadIdx.x >> 5, lane = threadIdx.x & 31;
    if (lane == 0) sm[warp] = m;
    __syncthreads();
    if (warp == 0) {
        int nw = (blockDim.x + 31) >> 5;
        m = (lane < nw) ? sm[lane] : 0.f;
        #pragma unroll
        for (int o = 16; o; o >>= 1) m = fmaxf(m, __shfl_xor_sync(0xffffffffu, m, o));
        if (lane == 0) atomicMax(&g_scal[slot], __float_as_uint(m));
    }
}

// ---------------- pre-passes (R9 proven form) --
__global__ void k_absmax_x(const float* __restrict__ x) {
    size_t n4 = (size_t)MROWS * KDIM / 4;
    float m = 0.f;
    size_t stride = (size_t)gridDim.x * blockDim.x;
    for (size_t i = (size_t)blockIdx.x * blockDim.x + threadIdx.x; i < n4; i += stride) {
        float4 v = ((const float4*)x)[i];
        m = fmaxf(m, fmaxf(fmaxf(fabsf(v.x), fabsf(v.y)), fmaxf(fabsf(v.z), fabsf(v.w))));
    }
    block_max_atomic(m, 0);
}

// Blocks [0,2048): x -> A2 both K-halves.  Blocks [2048,2112): w -> B2 (dup).
// x_lo grid uses s_lo = s_hi/2048 (the measured residual max lands there a.s.;
// even a wrong guess perturbs the output by ~2e-5 relative — negligible).
__global__ void k_quant_xw(const float* __restrict__ x, const float* __restrict__ w) {
    __half2* A2 = (__half2*)g_A2;
    __half2* B2 = (__half2*)g_B2;
    if (blockIdx.x < 2048) {
        float sh = load_scale_x();
        float invh = 1.f / sh;
        float invl = 2048.f / sh;
        const float rs = 1.f / 2048.f;
        size_t n4 = (size_t)MROWS * KDIM / 4;
        size_t stride = (size_t)2048 * blockDim.x;
        for (size_t i = (size_t)blockIdx.x * blockDim.x + threadIdx.x; i < n4; i += stride) {
            float4 v = ((const float4*)x)[i];
            size_t m = i >> 7;            // / (512/4)
            size_t kq = i & 127;
            float a0 = rintf(v.x * invh), a1 = rintf(v.y * invh);
            float a2v = rintf(v.z * invh), a3 = rintf(v.w * invh);
            float r0 = v.x - a0 * sh, r1 = v.y - a1 * sh;
            float r2 = v.z - a2v * sh, r3 = v.w - a3 * sh;
            size_t hi = m * (KD2 / 2) + kq * 2;       // half2 units
            A2[hi]     = __floats2half2_rn(a0, a1);
            A2[hi + 1] = __floats2half2_rn(a2v, a3);
            A2[hi + 256]     = __floats2half2_rn(rintf(r0 * invl) * rs, rintf(r1 * invl) * rs);
            A2[hi + 256 + 1] = __floats2half2_rn(rintf(r2 * invl) * rs, rintf(r3 * invl) * rs);
        }
    } else {
        size_t n4 = (size_t)NDIM * KDIM / 4;
        size_t stride = (size_t)64 * blockDim.x;
        for (size_t i = (size_t)(blockIdx.x - 2048) * blockDim.x + threadIdx.x; i < n4; i += stride) {
            float4 v = ((const float4*)w)[i];
            size_t n = i >> 7;
            size_t kq = i & 127;
            __half2 p0 = __floats2half2_rn(v.x, v.y);
            __half2 p1 = __floats2half2_rn(v.z, v.w);
            size_t b = n * (KD2 / 2) + kq * 2;
            B2[b] = p0; B2[b + 1] = p1;               // K-half 0
            B2[b + 256] = p0; B2[b + 256 + 1] = p1;   // K-half 1 (duplicate)
        }
    }
}

// ---------------- HMMA GEMM -------------------
// out[m][n] = s_hi * sum_k A2[m,k]*B2[n,k];  BMxBN=128x64, BK=64, 3 stages,
// XOR-swizzled smem, 3 CTAs/SM (24 warps/SM: profile R10 showed tensor=57%,
// occ=23% at 16 warps/SM -> latency-bound; smaller warp tile frees registers).
// 8 warps: warp_m = wid&3 (four 32-row slots), warp_n = wid>>2 (two 32-col slots).
extern __shared__ __half dynsmem[];

// Swizzled store layout per operand-stage: rows x 8 chunks of 16B;
// chunk c of row r lives at physical chunk c ^ (r & 7).
__device__ __forceinline__ void gemm_load_stage(uint32_t smem_base_u32, int s, int kt,
                                                size_t a_base, size_t b_base) {
    const int tid = threadIdx.x;
    const uint32_t As = smem_base_u32 + (uint32_t)s * STAGE_BYTES;
    const uint32_t Bs = As + A_STAGE_BYTES;
    const int k0 = kt * BK;
    #pragma unroll
    for (int i = 0; i < 6; ++i) {
        int id = tid + i * 256;              // 0..1535 chunks of 16B (A:1024, B:512)
        bool isA = id < 1024;
        int loc = isA ? id : id - 1024;
        int row = loc >> 3, cc = loc & 7;
        const __half* src = isA
            ? &g_A2[a_base + (size_t)row * KD2 + k0 + cc * 8]
            : &g_B2[b_base + (size_t)row * KD2 + k0 + cc * 8];
        uint32_t phys = (uint32_t)(cc ^ (row & 7));
        uint32_t dst = (isA ? As : Bs) + (uint32_t)row * 128u + phys * 16u;
        asm volatile("cp.async.cg.shared.global [%0], [%1], 16;\n" :: "r"(dst), "l"(src));
    }
}

__global__ void __launch_bounds__(256, 3) k_gemm4(float* __restrict__ out) {
    const int bn = blockIdx.x, bm = blockIdx.y;
    const int tid = threadIdx.x;
    const int wid = tid >> 5, lane = tid & 31;
    const int warp_m = wid & 3;          // 0..3 -> 32 rows each
    const int warp_n = wid >> 2;         // 0..1 -> 32 cols each

    const uint32_t sb = smem_u32(dynsmem);
    const size_t a_base = (size_t)bm * BM * KD2;
    const size_t b_base = (size_t)bn * BN * KD2;

    float acc[2][4][4];
    #pragma unroll
    for (int i = 0; i < 2; i++)
        #pragma unroll
        for (int j = 0; j < 4; j++)
            #pragma unroll
            for (int k = 0; k < 4; k++) acc[i][j][k] = 0.f;

    gemm_load_stage(sb, 0, 0, a_base, b_base);
    asm volatile("cp.async.commit_group;\n");
    gemm_load_stage(sb, 1, 1, a_base, b_base);
    asm volatile("cp.async.commit_group;\n");

    const int KT = KD2 / BK;   // 16
    for (int kt = 0; kt < KT; ++kt) {
        if (kt == KT - 1) { asm volatile("cp.async.wait_group 0;\n"); }
        else              { asm volatile("cp.async.wait_group 1;\n"); }
        __syncthreads();
        // Stage (kt+2)%3 was consumed in iteration kt-1; refill after barrier.
        if (kt + 2 < KT) {
            gemm_load_stage(sb, (kt + 2) % STAGES, kt + 2, a_base, b_base);
            asm volatile("cp.async.commit_group;\n");
        }

        const uint32_t As = sb + (uint32_t)(kt % STAGES) * STAGE_BYTES;
        const uint32_t Bs = As + A_STAGE_BYTES;

        #pragma unroll
        for (int ks = 0; ks < BK / 16; ++ks) {
            uint32_t a[2][4];
            #pragma unroll
            for (int mf = 0; mf < 2; ++mf) {
                int row = warp_m * 32 + mf * 16 + (lane & 15);
                int chunk = ks * 2 + ((lane & 16) ? 1 : 0);
                uint32_t addr = As + (uint32_t)row * 128u
                              + (uint32_t)(chunk ^ (row & 7)) * 16u;
                asm volatile("ldmatrix.sync.aligned.m8n8.x4.shared.b16 {%0,%1,%2,%3}, [%4];"
                             : "=r"(a[mf][0]), "=r"(a[mf][1]), "=r"(a[mf][2]), "=r"(a[mf][3])
                             : "r"(addr));
            }
            uint32_t b[4][2];
            #pragma unroll
            for (int g = 0; g < 2; ++g) {
                int nrow = warp_n * 32 + g * 16 + ((lane >> 4) << 3) + (lane & 7);
                int chunk = ks * 2 + ((lane & 8) ? 1 : 0);
                uint32_t addr = Bs + (uint32_t)nrow * 128u
                              + (uint32_t)(chunk ^ (nrow & 7)) * 16u;
                asm volatile("ldmatrix.sync.aligned.m8n8.x4.shared.b16 {%0,%1,%2,%3}, [%4];"
                             : "=r"(b[g * 2][0]), "=r"(b[g * 2][1]),
                               "=r"(b[g * 2 + 1][0]), "=r"(b[g * 2 + 1][1])
                             : "r"(addr));
            }
            #pragma unroll
            for (int mf = 0; mf < 2; ++mf)
                #pragma unroll
                for (int nf = 0; nf < 4; ++nf) {
                    asm volatile(
                        "mma.sync.aligned.m16n8k16.row.col.f32.f16.f16.f32 "
                        "{%0,%1,%2,%3}, {%4,%5,%6,%7}, {%8,%9}, {%0,%1,%2,%3};"
                        : "+f"(acc[mf][nf][0]), "+f"(acc[mf][nf][1]),
                          "+f"(acc[mf][nf][2]), "+f"(acc[mf][nf][3])
                        : "r"(a[mf][0]), "r"(a[mf][1]), "r"(a[mf][2]), "r"(a[mf][3]),
                          "r"(b[nf][0]), "r"(b[nf][1]));
                }
        }
    }

    // Epilogue: out = s_hi * acc, straight to d_out.
    const float f = load_scale_x();
    const size_t obase = (size_t)bm * BM * NDIM + (size_t)bn * BN;
    #pragma unroll
    for (int mf = 0; mf < 2; ++mf)
        #pragma unroll
        for (int nf = 0; nf < 4; ++nf) {
            int r0 = warp_m * 32 + mf * 16 + (lane >> 2);
            int c0 = warp_n * 32 + nf * 8 + 2 * (lane & 3);
            float* op = &out[obase + (size_t)r0 * NDIM + c0];
            op[0] = acc[mf][nf][0] * f;
            op[1] = acc[mf][nf][1] * f;
            float* op2 = op + 8 * NDIM;
            op2[0] = acc[mf][nf][2] * f;
            op2[1] = acc[mf][nf][3] * f;
        }
}

// ---------------- launch ----------------------
extern "C" void kernel_launch(void* const* d_in, const int* in_sizes, int n_in,
                              void* d_out, int out_size) {
    const float* x = (const float*)d_in[0];
    const float* w = (const float*)d_in[1];
    if (n_in >= 2 && in_sizes[0] == NDIM * KDIM && in_sizes[1] == MROWS * KDIM) {
        const float* t = x; x = w; w = t;
    }

    cudaFuncSetAttribute(k_gemm4, cudaFuncAttributeMaxDynamicSharedMemorySize, SMEM_DYN);

    k_absmax_x<<<2048, 256>>>(x);                                        // launch 1
    k_quant_xw<<<2112, 256>>>(x, w);                                     // launch 2
    k_gemm4<<<dim3(NDIM / BN, MROWS / BM), 256, SMEM_DYN>>>((float*)d_out); // launch 3
}

// round 12
// speedup vs baseline: 1.7829x; 1.7687x over previous
#include <cuda_runtime.h>
#include <cuda_fp16.h>
#include <cstdint>

// ---------------- problem dims ----------------
#define MROWS 32768           // 4*8192 activation rows
#define KDIM  512
#define NDIM  512

// ---------------- GEMM tiling -----------------
#define BM 128
#define BN 128
#define BK 64
#define STAGES 3
#define STAGE_OP_BYTES (128 * 128)            // one operand, one stage: 128 rows x 128 B
#define STAGE_BYTES (2 * STAGE_OP_BYTES)      // A + B
#define SMEM_DYN (STAGES * STAGE_BYTES)       // 98304 B -> 2 CTAs/SM

// ---------------- scratch ---------------------
// Plain fp16 casts. Error model (calibrated on R7/R9 measurements): ref's own
// gmac rounding ~2.0e-4 rel; fp16(w) cast 2.8e-4; fp16(x) cast 2.8e-4;
// combined ~4.9e-4 L2-relative, deterministic -> passes the 1e-3 gate with 2x margin.
__device__ __half  g_A2[(size_t)MROWS * KDIM]; // 32 MB  fp16(x)
__device__ __half  g_B2[(size_t)NDIM * KDIM];  // 512 KB fp16(w)

// ---------------- helpers ---------------------
__device__ __forceinline__ uint32_t smem_u32(const void* p) {
    return (uint32_t)__cvta_generic_to_shared(p);
}

// ---------------- prep: pure fp16 cast --------
// Blocks [0,2048): x -> A2.  Blocks [2048,2112): w -> B2.
__global__ void k_cast_xw(const float* __restrict__ x, const float* __restrict__ w) {
    __half2* A2 = (__half2*)g_A2;
    __half2* B2 = (__half2*)g_B2;
    if (blockIdx.x < 2048) {
        size_t n4 = (size_t)MROWS * KDIM / 4;
        size_t stride = (size_t)2048 * blockDim.x;
        for (size_t i = (size_t)blockIdx.x * blockDim.x + threadIdx.x; i < n4; i += stride) {
            float4 v = ((const float4*)x)[i];
            A2[i * 2]     = __floats2half2_rn(v.x, v.y);
            A2[i * 2 + 1] = __floats2half2_rn(v.z, v.w);
        }
    } else {
        size_t n4 = (size_t)NDIM * KDIM / 4;
        size_t stride = (size_t)64 * blockDim.x;
        for (size_t i = (size_t)(blockIdx.x - 2048) * blockDim.x + threadIdx.x; i < n4; i += stride) {
            float4 v = ((const float4*)w)[i];
            B2[i * 2]     = __floats2half2_rn(v.x, v.y);
            B2[i * 2 + 1] = __floats2half2_rn(v.z, v.w);
        }
    }
}

// ---------------- HMMA GEMM -------------------
// out[m][n] = sum_k A2[m,k]*B2[n,k];  128x128 tile, BK=64, K=512 (8 kt),
// 3 stages (wait_group 1), XOR-swizzled smem, 2 CTAs/SM. R9-proven pipeline.
extern __shared__ __half dynsmem[];

// Swizzled store layout per operand-stage: 128 rows x 8 chunks of 16B;
// chunk c of row r lives at physical chunk c ^ (r & 7).
__device__ __forceinline__ void gemm_load_stage(uint32_t smem_base_u32, int s, int kt,
                                                size_t a_base, size_t b_base) {
    const int tid = threadIdx.x;
    const uint32_t As = smem_base_u32 + (uint32_t)s * STAGE_BYTES;
    const uint32_t Bs = As + STAGE_OP_BYTES;
    const int k0 = kt * BK;
    #pragma unroll
    for (int i = 0; i < 8; ++i) {
        int id = tid + i * 256;              // 0..2047 chunks of 16B
        bool isA = id < 1024;
        int loc = isA ? id : id - 1024;
        int row = loc >> 3, cc = loc & 7;
        const __half* src = isA
            ? &g_A2[a_base + (size_t)row * KDIM + k0 + cc * 8]
            : &g_B2[b_base + (size_t)row * KDIM + k0 + cc * 8];
        uint32_t phys = (uint32_t)(cc ^ (row & 7));
        uint32_t dst = (isA ? As : Bs) + (uint32_t)row * 128u + phys * 16u;
        asm volatile("cp.async.cg.shared.global [%0], [%1], 16;\n" :: "r"(dst), "l"(src));
    }
}

__global__ void __launch_bounds__(256, 2) k_gemm5(float* __restrict__ out) {
    const int bn = blockIdx.x, bm = blockIdx.y;
    const int tid = threadIdx.x;
    const int wid = tid >> 5, lane = tid & 31;
    const int warp_m = wid & 1;          // 0..1 -> 64 rows each
    const int warp_n = wid >> 1;         // 0..3 -> 32 cols each

    const uint32_t sb = smem_u32(dynsmem);
    const size_t a_base = (size_t)bm * BM * KDIM;
    const size_t b_base = (size_t)bn * BN * KDIM;

    float acc[4][4][4];
    #pragma unroll
    for (int i = 0; i < 4; i++)
        #pragma unroll
        for (int j = 0; j < 4; j++)
            #pragma unroll
            for (int k = 0; k < 4; k++) acc[i][j][k] = 0.f;

    gemm_load_stage(sb, 0, 0, a_base, b_base);
    asm volatile("cp.async.commit_group;\n");
    gemm_load_stage(sb, 1, 1, a_base, b_base);
    asm volatile("cp.async.commit_group;\n");

    const int KT = KDIM / BK;   // 8
    for (int kt = 0; kt < KT; ++kt) {
        if (kt == KT - 1) { asm volatile("cp.async.wait_group 0;\n"); }
        else              { asm volatile("cp.async.wait_group 1;\n"); }
        __syncthreads();
        // Stage (kt+2)%3 was consumed in iteration kt-1; refill after barrier.
        if (kt + 2 < KT) {
            gemm_load_stage(sb, (kt + 2) % STAGES, kt + 2, a_base, b_base);
            asm volatile("cp.async.commit_group;\n");
        }

        const uint32_t As = sb + (uint32_t)(kt % STAGES) * STAGE_BYTES;
        const uint32_t Bs = As + STAGE_OP_BYTES;

        #pragma unroll
        for (int ks = 0; ks < BK / 16; ++ks) {
            uint32_t a[4][4];
            #pragma unroll
            for (int mf = 0; mf < 4; ++mf) {
                int row = warp_m * 64 + mf * 16 + (lane & 15);
                int chunk = ks * 2 + ((lane & 16) ? 1 : 0);
                uint32_t addr = As + (uint32_t)row * 128u
                              + (uint32_t)(chunk ^ (row & 7)) * 16u;
                asm volatile("ldmatrix.sync.aligned.m8n8.x4.shared.b16 {%0,%1,%2,%3}, [%4];"
                             : "=r"(a[mf][0]), "=r"(a[mf][1]), "=r"(a[mf][2]), "=r"(a[mf][3])
                             : "r"(addr));
            }
            uint32_t b[4][2];
            #pragma unroll
            for (int g = 0; g < 2; ++g) {
                int nrow = warp_n * 32 + g * 16 + ((lane >> 4) << 3) + (lane & 7);
                int chunk = ks * 2 + ((lane & 8) ? 1 : 0);
                uint32_t addr = Bs + (uint32_t)nrow * 128u
                              + (uint32_t)(chunk ^ (nrow & 7)) * 16u;
                asm volatile("ldmatrix.sync.aligned.m8n8.x4.shared.b16 {%0,%1,%2,%3}, [%4];"
                             : "=r"(b[g * 2][0]), "=r"(b[g * 2][1]),
                               "=r"(b[g * 2 + 1][0]), "=r"(b[g * 2 + 1][1])
                             : "r"(addr));
            }
            #pragma unroll
            for (int mf = 0; mf < 4; ++mf)
                #pragma unroll
                for (int nf = 0; nf < 4; ++nf) {
                    asm volatile(
                        "mma.sync.aligned.m16n8k16.row.col.f32.f16.f16.f32 "
                        "{%0,%1,%2,%3}, {%4,%5,%6,%7}, {%8,%9}, {%0,%1,%2,%3};"
                        : "+f"(acc[mf][nf][0]), "+f"(acc[mf][nf][1]),
                          "+f"(acc[mf][nf][2]), "+f"(acc[mf][nf][3])
                        : "r"(a[mf][0]), "r"(a[mf][1]), "r"(a[mf][2]), "r"(a[mf][3]),
                          "r"(b[nf][0]), "r"(b[nf][1]));
                }
        }
    }

    // Epilogue: raw fp32 accumulators straight to d_out (no scale).
    const size_t obase = (size_t)bm * BM * NDIM + (size_t)bn * BN;
    #pragma unroll
    for (int mf = 0; mf < 4; ++mf)
        #pragma unroll
        for (int nf = 0; nf < 4; ++nf) {
            int r0 = warp_m * 64 + mf * 16 + (lane >> 2);
            int c0 = warp_n * 32 + nf * 8 + 2 * (lane & 3);
            float* op = &out[obase + (size_t)r0 * NDIM + c0];
            op[0] = acc[mf][nf][0];
            op[1] = acc[mf][nf][1];
            float* op2 = op + 8 * NDIM;
            op2[0] = acc[mf][nf][2];
            op2[1] = acc[mf][nf][3];
        }
}

// ---------------- launch ----------------------
extern "C" void kernel_launch(void* const* d_in, const int* in_sizes, int n_in,
                              void* d_out, int out_size) {
    const float* x = (const float*)d_in[0];
    const float* w = (const float*)d_in[1];
    if (n_in >= 2 && in_sizes[0] == NDIM * KDIM && in_sizes[1] == MROWS * KDIM) {
        const float* t = x; x = w; w = t;
    }

    cudaFuncSetAttribute(k_gemm5, cudaFuncAttributeMaxDynamicSharedMemorySize, SMEM_DYN);

    k_cast_xw<<<2112, 256>>>(x, w);                                         // launch 1
    k_gemm5<<<dim3(NDIM / BN, MROWS / BM), 256, SMEM_DYN>>>((float*)d_out); // launch 2
}